// round 6
// baseline (speedup 1.0000x reference)
#include <cuda_runtime.h>
#include <math.h>

// Problem constants
#define NUM_R 8
#define KLEN  128
#define HID   32
#define LREC  4096
#define KP1   (KLEN + 1)
#define MAXB1 16

// Tier-1 table: g_T[b1][r][h] = ( vy*(A + inv*B), vy*A )
//   where A = PA[128] = sum_k W1[r,k,h], B = PB[128] = sum_k k*W1[r,k,h].
// Contribution of receiver r at kb==128: t.x + u * t.y
__device__ float2 g_T[MAXB1][NUM_R][HID];
// Raw prefix tables (PA, PB) for the general fallback path
__device__ float  g_P[NUM_R][KP1][2][HID];
// vy[b1][r] for the fallback path
__device__ float  g_vy[MAXB1][NUM_R];

// Table build: one block per (b1, r). Blocks with equal r write identical
// values to g_P (benign identical-value race); each block reads its own
// writes after __syncthreads.
__global__ void __launch_bounds__(256) prep_kernel(
    const float* __restrict__ W1, const float* __restrict__ rec)
{
    __shared__ float sTA[8][HID];
    __shared__ float sTB[8][HID];
    int r   = blockIdx.x & (NUM_R - 1);
    int b1  = blockIdx.x >> 3;
    int h   = threadIdx.x & 31;
    int seg = threadIdx.x >> 5;   // 0..7, 16 k's each
    const float inv = 1.0f / 16384.0f;

    int k0 = seg * 16;
    float a = 0.f, b = 0.f;
    if (seg == 0) { g_P[r][0][0][h] = 0.f; g_P[r][0][1][h] = 0.f; }
#pragma unroll
    for (int j = 0; j < 16; ++j) {
        int k = k0 + j;
        float w = W1[(r * KLEN + k) * HID + h];
        a += w;
        b += (float)k * w;
        g_P[r][k + 1][0][h] = a;
        g_P[r][k + 1][1][h] = b;
    }
    sTA[seg][h] = a;
    sTB[seg][h] = b;
    __syncthreads();

    float offA = 0.f, offB = 0.f;
    for (int s = 0; s < seg; ++s) { offA += sTA[s][h]; offB += sTB[s][h]; }
    if (seg > 0) {
#pragma unroll
        for (int j = 0; j < 16; ++j) {
            int k = k0 + j;
            g_P[r][k + 1][0][h] += offA;
            g_P[r][k + 1][1][h] += offB;
        }
    }
    __syncthreads();

    const float* rr = rec + (size_t)(b1 * NUM_R + r) * LREC;
    float vy = 0.5f * rr[2047] + 0.5f * rr[2048];
    if (threadIdx.x == 0) g_vy[b1][r] = vy;

    if (seg == 0) {   // first warp writes the tier-1 entry
        float Aend = g_P[r][KLEN][0][h];
        float Bend = g_P[r][KLEN][1][h];
        float2 t;
        t.x = vy * fmaf(inv, Bend, Aend);   // vy*(A + inv*B)
        t.y = vy * Aend;
        g_T[b1][r][h] = t;
    }
}

// Fused main kernel, warp-autonomous: 32 lanes = 4 samples x 8 receivers.
// Phase 1 (per lane): geometry -> u into 128B of warp-private smem.
// Phase 2 (per lane = hidden unit h): acc_s = CX + sum_r u[s][r]*CY[r].
__global__ void __launch_bounds__(256) tof_kernel(
    const float* __restrict__ sloc,   // (B1*B2, 3)
    const float* __restrict__ emit,   // (3,)
    const float* __restrict__ rloc,   // (R, 3)
    const float* __restrict__ b1v,    // (HID,)
    const float* __restrict__ W2,     // (HID,)
    const float* __restrict__ b2v,    // (1,)
    float* __restrict__ out,          // (B1*B2,)
    int total, int b2n)
{
    __shared__ float su[8][NUM_R][4];   // [warp][r][s], 16B-aligned rows

    int tid  = threadIdx.x;
    int wid  = tid >> 5;
    int lane = tid & 31;
    int s_local = lane >> 3;            // 0..3: which of my warp's samples
    int r_mine  = lane & 7;             // 0..7: which receiver
    int s0g = (int)blockIdx.x * 32 + wid * 4;   // warp's global sample base
    int sample = s0g + s_local;
    const float inv = 1.0f / 16384.0f;

    int b1w = (int)((unsigned)s0g / (unsigned)b2n);

    // ---- Phase 1: geometry (one (sample, r) pair per lane) ----
    bool ok = true;
    float u = 0.f;
    if (sample < total) {
        int b1 = (int)((unsigned)sample / (unsigned)b2n);
        const float* sp = sloc + (size_t)sample * 3;
        float sx = sp[0], sy = sp[1], sz = sp[2];
        float dx = sx - emit[0], dy = sy - emit[1], dz = sz - emit[2];
        float de = sqrtf(dx * dx + dy * dy + dz * dz);
        const float* rp = rloc + r_mine * 3;
        float qx = sx - rp[0], qy = sy - rp[1], qz = sz - rp[2];
        float dr = sqrtf(qx * qx + qy * qy + qz * qz);
        float tt = (de + dr) / 343.0f * 96000.0f;   // exact reference order
        int cs = (int)rintf(tt) - (KLEN / 2);
        int m0 = 4 * cs - 8192;
        u = (float)m0 * inv;                        // exact
        // tier-1 valid iff kb saturates at 128 (m0 <= -128), in range,
        // and warp has a uniform b1
        ok = (m0 >= -16384) && (m0 <= -KLEN) && (b1 == b1w);
    }
    su[wid][r_mine][s_local] = u;
    bool fast = __all_sync(0xffffffffu, ok);
    __syncwarp();

    // ---- Phase 2 ----
    float acc0, acc1, acc2, acc3;
    if (fast) {
        // preload warp-invariant coefficients (uniform, L1-hot)
        float cy[NUM_R];
        float cx = 0.f;
#pragma unroll
        for (int r = 0; r < NUM_R; ++r) {
            float2 t = g_T[b1w][r][lane];
            cx += t.x;
            cy[r] = t.y;
        }
        acc0 = cx; acc1 = cx; acc2 = cx; acc3 = cx;
#pragma unroll
        for (int r = 0; r < NUM_R; ++r) {
            float4 us = *(const float4*)&su[wid][r][0];   // u[s=0..3]
            acc0 = fmaf(us.x, cy[r], acc0);
            acc1 = fmaf(us.y, cy[r], acc1);
            acc2 = fmaf(us.z, cy[r], acc2);
            acc3 = fmaf(us.w, cy[r], acc3);
        }
    } else {
        // General fallback: reconstruct m0 exactly from u; full clamped form.
        float accs[4];
#pragma unroll
        for (int j = 0; j < 4; ++j) {
            accs[j] = 0.f;
            int s = s0g + j;
            if (s >= total) continue;
            int b1 = (int)((unsigned)s / (unsigned)b2n);
            float a = 0.f;
#pragma unroll
            for (int r = 0; r < NUM_R; ++r) {
                float uu = su[wid][r][j];
                int m0 = __float2int_rn(uu * 16384.0f);
                float vy = g_vy[b1][r];
                int ka = max(min(-16384 - m0, KLEN), 0);
                int kb = max(min(-m0,          KLEN), 0);
                int kd = max(min(16384 - m0,   KLEN), 0);
                float m0f = (float)m0;
                if (kb > ka) {
                    float pa = g_P[r][kb][0][lane] - g_P[r][ka][0][lane];
                    float pb = g_P[r][kb][1][lane] - g_P[r][ka][1][lane];
                    a += vy * (fmaf(m0f, inv, 1.0f) * pa + inv * pb);
                }
                if (kd > kb) {
                    float pa = g_P[r][kd][0][lane] - g_P[r][kb][0][lane];
                    float pb = g_P[r][kd][1][lane] - g_P[r][kb][1][lane];
                    a += vy * (fmaf(-m0f, inv, 1.0f) * pa - inv * pb);
                }
            }
            accs[j] = a;
        }
        acc0 = accs[0]; acc1 = accs[1]; acc2 = accs[2]; acc3 = accs[3];
    }

    // ---- MLP head: relu(acc + b1) * W2, merged 4-sample warp reduction ----
    float blane = b1v[lane];
    float wlane = W2[lane];
    float c0 = fmaxf(acc0 + blane, 0.f) * wlane;
    float c1 = fmaxf(acc1 + blane, 0.f) * wlane;
    float c2 = fmaxf(acc2 + blane, 0.f) * wlane;
    float c3 = fmaxf(acc3 + blane, 0.f) * wlane;

    float t0 = __shfl_xor_sync(0xffffffffu, c0, 16);
    float t1 = __shfl_xor_sync(0xffffffffu, c1, 16);
    float t2 = __shfl_xor_sync(0xffffffffu, c2, 16);
    float t3 = __shfl_xor_sync(0xffffffffu, c3, 16);
    bool lo16 = lane < 16;
    float v = lo16 ? (c0 + t0) : (c1 + t1);   // lanes0-15: s0, 16-31: s1
    float w = lo16 ? (c2 + t2) : (c3 + t3);   // lanes0-15: s2, 16-31: s3
    float tv = __shfl_xor_sync(0xffffffffu, v, 8);
    float tw = __shfl_xor_sync(0xffffffffu, w, 8);
    float z = ((lane & 8) == 0) ? (v + tv) : (w + tw);
    // lanes 0-7: s0, 8-15: s2, 16-23: s1, 24-31: s3
    z += __shfl_xor_sync(0xffffffffu, z, 4);
    z += __shfl_xor_sync(0xffffffffu, z, 2);
    z += __shfl_xor_sync(0xffffffffu, z, 1);

    if ((lane & 7) == 0) {
        int j = ((lane >> 2) & 2) | (lane >> 4);   // 0->0, 8->2, 16->1, 24->3
        int idx = s0g + j;
        if (idx < total) out[idx] = z + b2v[0];
    }
}

extern "C" void kernel_launch(void* const* d_in, const int* in_sizes, int n_in,
                              void* d_out, int out_size) {
    const float* rec  = (const float*)d_in[0];
    const float* sloc = (const float*)d_in[1];
    const float* emit = (const float*)d_in[2];
    const float* rloc = (const float*)d_in[3];
    const float* W1   = (const float*)d_in[4];
    const float* b1v  = (const float*)d_in[5];
    const float* W2   = (const float*)d_in[6];
    const float* b2v  = (const float*)d_in[7];
    float* out = (float*)d_out;

    int nb1 = in_sizes[0] / (NUM_R * LREC);       // B1
    if (nb1 < 1) nb1 = 1;
    if (nb1 > MAXB1) nb1 = MAXB1;
    int total = out_size;                         // B1*B2 samples
    int b2n = total / nb1;

    prep_kernel<<<NUM_R * nb1, 256>>>(W1, rec);

    int blocks = (total + 31) / 32;
    tof_kernel<<<blocks, 256>>>(sloc, emit, rloc, b1v, W2, b2v, out,
                                total, b2n);
}

// round 8
// speedup vs baseline: 1.5209x; 1.5209x over previous
#include <cuda_runtime.h>
#include <math.h>

// Problem constants
#define NUM_R 8
#define KLEN  128
#define HID   32
#define LREC  4096
#define KP1   (KLEN + 1)
#define MAXB1 16
#define SPB   64              // samples per block (8 warps x 8 samples)

// Fast-path folded table: contribution of receiver r, batch b1:
//   S = c.x + u * c.y   (vy baked in)
__device__ float2 g_C[MAXB1][NUM_R][KP1][HID];
// Raw prefix tables (PA, PB) for the general fallback path (also prep scratch)
__device__ float  g_P[NUM_R][KP1][2][HID];
// vy[b1][r] for the fallback path
__device__ float  g_vy[MAXB1][NUM_R];

// Table build: one block per (b1, r). Blocks with equal r write identical
// values to g_P (benign identical-value race); each block reads its own
// writes after __syncthreads.
__global__ void __launch_bounds__(256) prep_kernel(
    const float* __restrict__ W1, const float* __restrict__ rec)
{
    __shared__ float sTA[8][HID];
    __shared__ float sTB[8][HID];
    int r   = blockIdx.x & (NUM_R - 1);
    int b1  = blockIdx.x >> 3;
    int h   = threadIdx.x & 31;
    int seg = threadIdx.x >> 5;   // 0..7, 16 k's each
    const float inv = 1.0f / 16384.0f;

    int k0 = seg * 16;
    float a = 0.f, b = 0.f;
    if (seg == 0) { g_P[r][0][0][h] = 0.f; g_P[r][0][1][h] = 0.f; }
#pragma unroll
    for (int j = 0; j < 16; ++j) {
        int k = k0 + j;
        float w = W1[(r * KLEN + k) * HID + h];
        a += w;
        b += (float)k * w;
        g_P[r][k + 1][0][h] = a;
        g_P[r][k + 1][1][h] = b;
    }
    sTA[seg][h] = a;
    sTB[seg][h] = b;
    __syncthreads();

    float offA = 0.f, offB = 0.f;
    for (int s = 0; s < seg; ++s) { offA += sTA[s][h]; offB += sTB[s][h]; }
    if (seg > 0) {
#pragma unroll
        for (int j = 0; j < 16; ++j) {
            int k = k0 + j;
            g_P[r][k + 1][0][h] += offA;
            g_P[r][k + 1][1][h] += offB;
        }
    }
    __syncthreads();

    const float* rr = rec + (size_t)(b1 * NUM_R + r) * LREC;
    float vy = 0.5f * rr[2047] + 0.5f * rr[2048];
    if (threadIdx.x == 0) g_vy[b1][r] = vy;

    const float inv2 = 2.0f / 16384.0f;
    float Aend = g_P[r][KLEN][0][h];
    float Bend = g_P[r][KLEN][1][h];
    float Base = fmaf(-inv, Bend, Aend);
    for (int k = seg; k < KP1; k += 8) {
        float pa = g_P[r][k][0][h], pb = g_P[r][k][1][h];
        float2 c;
        c.x = vy * fmaf(inv2, pb, Base);
        c.y = vy * fmaf(2.0f, pa, -Aend);
        g_C[b1][r][k][h] = c;
    }
}

// Fused main kernel: 256 threads = 64 samples.
// Phase 1: thread handles 2 (sample, r) geometry tasks -> smem (off, u).
// Phase 2: each warp handles 8 samples; lane = hidden unit.
__global__ void __launch_bounds__(256) tof_kernel(
    const float* __restrict__ sloc,   // (B1*B2, 3)
    const float* __restrict__ emit,   // (3,)
    const float* __restrict__ rloc,   // (R, 3)
    const float* __restrict__ b1v,    // (HID,)
    const float* __restrict__ W2,     // (HID,)
    const float* __restrict__ b2v,    // (1,)
    float* __restrict__ out,          // (B1*B2,)
    int total, int b2n, int b1shift)
{
    __shared__ float2 sg[SPB][NUM_R];
    __shared__ int s_bad;

    int tid   = threadIdx.x;
    int bbase = (int)blockIdx.x * SPB;
    const float inv = 1.0f / 16384.0f;

    if (tid == 0) s_bad = 0;
    __syncthreads();

    // ---- Phase 1: geometry, 2 tasks per thread ----
    float ex = emit[0], ey = emit[1], ez = emit[2];
#pragma unroll
    for (int half = 0; half < 2; ++half) {
        int task = tid + half * 256;          // 0..511
        int s_local = task >> 3;
        int r = task & 7;
        int sample = bbase + s_local;
        if (sample < total) {
            int b1 = (b1shift >= 0) ? (sample >> b1shift)
                                    : (int)((unsigned)sample / (unsigned)b2n);
            const float* sp = sloc + (size_t)sample * 3;
            float sx = sp[0], sy = sp[1], sz = sp[2];
            float dx = sx - ex, dy = sy - ey, dz = sz - ez;
            float de = sqrtf(dx * dx + dy * dy + dz * dz);
            const float* rp = rloc + r * 3;
            float qx = sx - rp[0], qy = sy - rp[1], qz = sz - rp[2];
            float dr = sqrtf(qx * qx + qy * qy + qz * qz);
            float tt = (de + dr) / 343.0f * 96000.0f;  // exact reference order
            int cs = (int)rintf(tt) - (KLEN / 2);
            int m0 = 4 * cs - 8192;
            int kb = max(min(-m0, KLEN), 0);
            bool ok = (m0 >= -16384) && (m0 <= 16384 - KLEN);
            int off = ((b1 * NUM_R + r) * KP1 + kb) * (HID * 8);  // bytes
            sg[s_local][r] = make_float2(__int_as_float(off), (float)m0 * inv);
            if (!ok) atomicOr(&s_bad, 1);
        } else {
            sg[s_local][r] = make_float2(__int_as_float(0), 0.f);
        }
    }
    __syncthreads();

    // ---- Phase 2: table accumulation, 8 samples per warp ----
    int wid  = tid >> 5;
    int lane = tid & 31;
    int s0 = wid * 8;                   // local sample base for this warp
    int s0g = bbase + s0;
    bool bad = (s_bad != 0);

    float acc[8];
    const char* basep = (const char*)(&g_C[0][0][0][0]) + lane * 8;

    if (!bad) {
#pragma unroll
        for (int j = 0; j < 8; ++j) acc[j] = 0.f;
#pragma unroll
        for (int r = 0; r < NUM_R; ++r) {
#pragma unroll
            for (int j = 0; j < 8; ++j) {
                float2 g = sg[s0 + j][r];
                float2 c = *(const float2*)(basep + __float_as_int(g.x));
                acc[j] = fmaf(g.y, c.y, acc[j] + c.x);
            }
        }
    } else {
        // General fallback (rare): reconstruct m0 exactly from u.
        for (int j = 0; j < 8; ++j) {
            acc[j] = 0.f;
            int sample = s0g + j;
            if (sample >= total) continue;
            int b1 = (b1shift >= 0) ? (sample >> b1shift)
                                    : (int)((unsigned)sample / (unsigned)b2n);
            float a = 0.f;
            for (int r = 0; r < NUM_R; ++r) {
                float2 g = sg[s0 + j][r];
                int m0 = __float2int_rn(g.y * 16384.0f);
                float vy = g_vy[b1][r];
                int ka = max(min(-16384 - m0, KLEN), 0);
                int kb = max(min(-m0,          KLEN), 0);
                int kd = max(min(16384 - m0,   KLEN), 0);
                float m0f = (float)m0;
                if (kb > ka) {
                    float pa = g_P[r][kb][0][lane] - g_P[r][ka][0][lane];
                    float pb = g_P[r][kb][1][lane] - g_P[r][ka][1][lane];
                    a += vy * (fmaf(m0f, inv, 1.0f) * pa + inv * pb);
                }
                if (kd > kb) {
                    float pa = g_P[r][kd][0][lane] - g_P[r][kb][0][lane];
                    float pb = g_P[r][kd][1][lane] - g_P[r][kb][1][lane];
                    a += vy * (fmaf(-m0f, inv, 1.0f) * pa - inv * pb);
                }
            }
            acc[j] = a;
        }
    }

    // ---- MLP head: relu(acc + b1) * W2, merged 8-sample reduction ----
    // ALL shuffles are issued unconditionally (no shuffle inside a ternary);
    // ternaries select only between already-computed lane-local sums.
    float blane = b1v[lane];
    float wlane = W2[lane];
    float b2s   = b2v[0];

    float c0 = fmaxf(acc[0] + blane, 0.f) * wlane;
    float c1 = fmaxf(acc[1] + blane, 0.f) * wlane;
    float c2 = fmaxf(acc[2] + blane, 0.f) * wlane;
    float c3 = fmaxf(acc[3] + blane, 0.f) * wlane;
    float c4 = fmaxf(acc[4] + blane, 0.f) * wlane;
    float c5 = fmaxf(acc[5] + blane, 0.f) * wlane;
    float c6 = fmaxf(acc[6] + blane, 0.f) * wlane;
    float c7 = fmaxf(acc[7] + blane, 0.f) * wlane;

    // Step 1 (xor 16): 8 -> 4
    float t0 = __shfl_xor_sync(~0u, c0, 16);
    float t1 = __shfl_xor_sync(~0u, c1, 16);
    float t2 = __shfl_xor_sync(~0u, c2, 16);
    float t3 = __shfl_xor_sync(~0u, c3, 16);
    float t4 = __shfl_xor_sync(~0u, c4, 16);
    float t5 = __shfl_xor_sync(~0u, c5, 16);
    float t6 = __shfl_xor_sync(~0u, c6, 16);
    float t7 = __shfl_xor_sync(~0u, c7, 16);
    bool lo16 = lane < 16;
    float v0 = lo16 ? (c0 + t0) : (c1 + t1);   // b4=0: s0, b4=1: s1
    float v1 = lo16 ? (c2 + t2) : (c3 + t3);   // s2 / s3
    float v2 = lo16 ? (c4 + t4) : (c5 + t5);   // s4 / s5
    float v3 = lo16 ? (c6 + t6) : (c7 + t7);   // s6 / s7

    // Step 2 (xor 8): 4 -> 2
    float u0 = __shfl_xor_sync(~0u, v0, 8);
    float u1 = __shfl_xor_sync(~0u, v1, 8);
    float u2 = __shfl_xor_sync(~0u, v2, 8);
    float u3 = __shfl_xor_sync(~0u, v3, 8);
    bool lo8 = (lane & 8) == 0;
    float w0 = lo8 ? (v0 + u0) : (v1 + u1);
    float w1 = lo8 ? (v2 + u2) : (v3 + u3);

    // Step 3 (xor 4): 2 -> 1
    float x0 = __shfl_xor_sync(~0u, w0, 4);
    float x1 = __shfl_xor_sync(~0u, w1, 4);
    bool lo4 = (lane & 4) == 0;
    float z = lo4 ? (w0 + x0) : (w1 + x1);

    // Final butterflies within groups of 4
    z += __shfl_xor_sync(~0u, z, 2);
    z += __shfl_xor_sync(~0u, z, 1);

    // Lane 4g holds sample bitrev3(g): sample = bit2*4 + bit3*2 + bit4
    if ((lane & 3) == 0) {
        int g = lane >> 2;
        int j = ((g & 1) << 2) | (g & 2) | (g >> 2);
        int idx = s0g + j;
        if (idx < total) out[idx] = z + b2s;
    }
}

extern "C" void kernel_launch(void* const* d_in, const int* in_sizes, int n_in,
                              void* d_out, int out_size) {
    const float* rec  = (const float*)d_in[0];
    const float* sloc = (const float*)d_in[1];
    const float* emit = (const float*)d_in[2];
    const float* rloc = (const float*)d_in[3];
    const float* W1   = (const float*)d_in[4];
    const float* b1v  = (const float*)d_in[5];
    const float* W2   = (const float*)d_in[6];
    const float* b2v  = (const float*)d_in[7];
    float* out = (float*)d_out;

    int nb1 = in_sizes[0] / (NUM_R * LREC);       // B1
    if (nb1 < 1) nb1 = 1;
    if (nb1 > MAXB1) nb1 = MAXB1;
    int total = out_size;                         // B1*B2 samples
    int b2n = total / nb1;

    int b1shift = -1;
    if (b2n > 0 && (b2n & (b2n - 1)) == 0) {
        b1shift = 0;
        while ((1 << b1shift) != b2n) ++b1shift;
    }

    prep_kernel<<<NUM_R * nb1, 256>>>(W1, rec);

    int blocks = (total + SPB - 1) / SPB;
    tof_kernel<<<blocks, 256>>>(sloc, emit, rloc, b1v, W2, b2v, out,
                                total, b2n, b1shift);
}

// round 9
// speedup vs baseline: 1.7028x; 1.1196x over previous
#include <cuda_runtime.h>
#include <math.h>

// Problem constants
#define NUM_R 8
#define KLEN  128
#define HID   32
#define LREC  4096
#define KP1   (KLEN + 1)
#define MAXB1 16
#define SPB   32              // samples per block (8 warps x 4 samples)

// Fast-path folded table: contribution of receiver r, batch b1:
//   S = c.x + u * c.y   (vy baked in)
__device__ float2 g_C[MAXB1][NUM_R][KP1][HID];
// Raw prefix tables (PA, PB) for the general fallback path (also prep scratch)
__device__ float  g_P[NUM_R][KP1][2][HID];
// vy[b1][r] for the fallback path
__device__ float  g_vy[MAXB1][NUM_R];

// Table build: one block per (b1, r). Blocks with equal r write identical
// values to g_P (benign identical-value race); each block reads its own
// writes after __syncthreads.
__global__ void __launch_bounds__(256) prep_kernel(
    const float* __restrict__ W1, const float* __restrict__ rec)
{
    __shared__ float sTA[8][HID];
    __shared__ float sTB[8][HID];
    int r   = blockIdx.x & (NUM_R - 1);
    int b1  = blockIdx.x >> 3;
    int h   = threadIdx.x & 31;
    int seg = threadIdx.x >> 5;   // 0..7, 16 k's each
    const float inv = 1.0f / 16384.0f;

    int k0 = seg * 16;
    float a = 0.f, b = 0.f;
    if (seg == 0) { g_P[r][0][0][h] = 0.f; g_P[r][0][1][h] = 0.f; }
#pragma unroll
    for (int j = 0; j < 16; ++j) {
        int k = k0 + j;
        float w = W1[(r * KLEN + k) * HID + h];
        a += w;
        b += (float)k * w;
        g_P[r][k + 1][0][h] = a;
        g_P[r][k + 1][1][h] = b;
    }
    sTA[seg][h] = a;
    sTB[seg][h] = b;
    __syncthreads();

    float offA = 0.f, offB = 0.f;
    for (int s = 0; s < seg; ++s) { offA += sTA[s][h]; offB += sTB[s][h]; }
    if (seg > 0) {
#pragma unroll
        for (int j = 0; j < 16; ++j) {
            int k = k0 + j;
            g_P[r][k + 1][0][h] += offA;
            g_P[r][k + 1][1][h] += offB;
        }
    }
    __syncthreads();

    const float* rr = rec + (size_t)(b1 * NUM_R + r) * LREC;
    float vy = 0.5f * rr[2047] + 0.5f * rr[2048];
    if (threadIdx.x == 0) g_vy[b1][r] = vy;

    const float inv2 = 2.0f / 16384.0f;
    float Aend = g_P[r][KLEN][0][h];
    float Bend = g_P[r][KLEN][1][h];
    float Base = fmaf(-inv, Bend, Aend);
    for (int k = seg; k < KP1; k += 8) {
        float pa = g_P[r][k][0][h], pb = g_P[r][k][1][h];
        float2 c;
        c.x = vy * fmaf(inv2, pb, Base);
        c.y = vy * fmaf(2.0f, pa, -Aend);
        g_C[b1][r][k][h] = c;
    }
    // Signal PDL dependents (tof) that our global stores are ready.
    asm volatile("griddepcontrol.launch_dependents;" ::: "memory");
}

// Fused main kernel: 256 threads = 32 samples.
// Phase 1: thread (s_local, r) computes geometry -> smem (off, u).
//          (independent of prep's outputs -> overlaps prep via PDL)
// Phase 2: after griddepcontrol.wait, each warp handles 4 samples.
__global__ void __launch_bounds__(256) tof_kernel(
    const float* __restrict__ sloc,   // (B1*B2, 3)
    const float* __restrict__ emit,   // (3,)
    const float* __restrict__ rloc,   // (R, 3)
    const float* __restrict__ b1v,    // (HID,)
    const float* __restrict__ W2,     // (HID,)
    const float* __restrict__ b2v,    // (1,)
    float* __restrict__ out,          // (B1*B2,)
    int total, int b2n, int b1shift)
{
    __shared__ __align__(16) float2 sg[SPB][NUM_R];
    __shared__ int s_bad;

    int tid   = threadIdx.x;
    int bbase = (int)blockIdx.x * SPB;
    const float inv = 1.0f / 16384.0f;
    const float SCALE = 96000.0f / 343.0f;

    if (tid == 0) s_bad = 0;

    // ---- Phase 1: geometry (one (sample, r) pair per thread) ----
    {
        int s_local = tid >> 3;
        int r = tid & 7;
        int sample = bbase + s_local;
        if (sample < total) {
            int b1 = (b1shift >= 0) ? (sample >> b1shift)
                                    : (int)((unsigned)sample / (unsigned)b2n);
            const float* sp = sloc + (size_t)sample * 3;
            float sx = sp[0], sy = sp[1], sz = sp[2];
            float dx = sx - emit[0], dy = sy - emit[1], dz = sz - emit[2];
            float de = sqrtf(dx * dx + dy * dy + dz * dz);
            const float* rp = rloc + r * 3;
            float qx = sx - rp[0], qy = sy - rp[1], qz = sz - rp[2];
            float dr = sqrtf(qx * qx + qy * qy + qz * qz);
            float tt = (de + dr) * SCALE;
            int cs = (int)rintf(tt) - (KLEN / 2);
            int m0 = 4 * cs - 8192;
            int kb = max(min(-m0, KLEN), 0);
            bool ok = (m0 >= -16384) && (m0 <= 16384 - KLEN);
            int off = ((b1 * NUM_R + r) * KP1 + kb) * (HID * 8);  // bytes
            sg[s_local][r] = make_float2(__int_as_float(off), (float)m0 * inv);
            if (!ok) s_bad = 1;          // benign race, only writes 1
        } else {
            sg[s_local][r] = make_float2(__int_as_float(0), 0.f);
        }
    }
    __syncthreads();
    // Wait for prep's tables (PDL). No-op when launched without PDL.
    asm volatile("griddepcontrol.wait;" ::: "memory");

    // ---- Phase 2: table accumulation, 4 samples per warp ----
    int wid  = tid >> 5;
    int lane = tid & 31;
    int s0 = wid * 4;                   // local sample base for this warp
    int s0g = bbase + s0;
    bool bad = (s_bad != 0);

    float acc0 = 0.f, acc1 = 0.f, acc2 = 0.f, acc3 = 0.f;
    const char* basep = (const char*)(&g_C[0][0][0][0]) + lane * 8;

    if (!bad) {
        const float4* row0 = (const float4*)&sg[s0 + 0][0];  // 4 float4 = 8 (off,u)
        const float4* row1 = (const float4*)&sg[s0 + 1][0];
        const float4* row2 = (const float4*)&sg[s0 + 2][0];
        const float4* row3 = (const float4*)&sg[s0 + 3][0];
#pragma unroll
        for (int r2 = 0; r2 < 4; ++r2) {       // two receivers per iteration
            float4 a = row0[r2], b = row1[r2], c = row2[r2], d = row3[r2];
            float2 ca0 = *(const float2*)(basep + __float_as_int(a.x));
            float2 cb0 = *(const float2*)(basep + __float_as_int(b.x));
            float2 cc0 = *(const float2*)(basep + __float_as_int(c.x));
            float2 cd0 = *(const float2*)(basep + __float_as_int(d.x));
            float2 ca1 = *(const float2*)(basep + __float_as_int(a.z));
            float2 cb1 = *(const float2*)(basep + __float_as_int(b.z));
            float2 cc1 = *(const float2*)(basep + __float_as_int(c.z));
            float2 cd1 = *(const float2*)(basep + __float_as_int(d.z));
            acc0 = fmaf(a.y, ca0.y, acc0 + ca0.x);
            acc1 = fmaf(b.y, cb0.y, acc1 + cb0.x);
            acc2 = fmaf(c.y, cc0.y, acc2 + cc0.x);
            acc3 = fmaf(d.y, cd0.y, acc3 + cd0.x);
            acc0 = fmaf(a.w, ca1.y, acc0 + ca1.x);
            acc1 = fmaf(b.w, cb1.y, acc1 + cb1.x);
            acc2 = fmaf(c.w, cc1.y, acc2 + cc1.x);
            acc3 = fmaf(d.w, cd1.y, acc3 + cd1.x);
        }
    } else {
        // General fallback (rare): reconstruct m0 exactly from u.
        float accs[4];
        for (int j = 0; j < 4; ++j) {
            accs[j] = 0.f;
            int sample = s0g + j;
            if (sample >= total) continue;
            int b1 = (b1shift >= 0) ? (sample >> b1shift)
                                    : (int)((unsigned)sample / (unsigned)b2n);
            float a = 0.f;
            for (int r = 0; r < NUM_R; ++r) {
                float2 g = sg[s0 + j][r];
                int m0 = __float2int_rn(g.y * 16384.0f);
                float vy = g_vy[b1][r];
                int ka = max(min(-16384 - m0, KLEN), 0);
                int kb = max(min(-m0,          KLEN), 0);
                int kd = max(min(16384 - m0,   KLEN), 0);
                float m0f = (float)m0;
                if (kb > ka) {
                    float pa = g_P[r][kb][0][lane] - g_P[r][ka][0][lane];
                    float pb = g_P[r][kb][1][lane] - g_P[r][ka][1][lane];
                    a += vy * (fmaf(m0f, inv, 1.0f) * pa + inv * pb);
                }
                if (kd > kb) {
                    float pa = g_P[r][kd][0][lane] - g_P[r][kb][0][lane];
                    float pb = g_P[r][kd][1][lane] - g_P[r][kb][1][lane];
                    a += vy * (fmaf(-m0f, inv, 1.0f) * pa - inv * pb);
                }
            }
            accs[j] = a;
        }
        acc0 = accs[0]; acc1 = accs[1]; acc2 = accs[2]; acc3 = accs[3];
    }

    // ---- MLP head: relu(acc + b1) * W2, merged 4-sample warp reduction ----
    // (proven R5 form: all shuffles unconditional, ternaries select sums only)
    float blane = b1v[lane];
    float wlane = W2[lane];
    float b2s   = b2v[0];

    float c0 = fmaxf(acc0 + blane, 0.f) * wlane;
    float c1 = fmaxf(acc1 + blane, 0.f) * wlane;
    float c2 = fmaxf(acc2 + blane, 0.f) * wlane;
    float c3 = fmaxf(acc3 + blane, 0.f) * wlane;

    float t0 = __shfl_xor_sync(0xffffffffu, c0, 16);
    float t1 = __shfl_xor_sync(0xffffffffu, c1, 16);
    float t2 = __shfl_xor_sync(0xffffffffu, c2, 16);
    float t3 = __shfl_xor_sync(0xffffffffu, c3, 16);
    bool lo16 = lane < 16;
    float v = lo16 ? (c0 + t0) : (c1 + t1);   // lanes0-15: s0, 16-31: s1
    float w = lo16 ? (c2 + t2) : (c3 + t3);   // lanes0-15: s2, 16-31: s3
    float tv = __shfl_xor_sync(0xffffffffu, v, 8);
    float tw = __shfl_xor_sync(0xffffffffu, w, 8);
    float z = ((lane & 8) == 0) ? (v + tv) : (w + tw);
    // lanes 0-7: s0, 8-15: s2, 16-23: s1, 24-31: s3
    z += __shfl_xor_sync(0xffffffffu, z, 4);
    z += __shfl_xor_sync(0xffffffffu, z, 2);
    z += __shfl_xor_sync(0xffffffffu, z, 1);

    if ((lane & 7) == 0) {
        int j = ((lane >> 2) & 2) | (lane >> 4);   // 0->0, 8->2, 16->1, 24->3
        int idx = s0g + j;
        if (idx < total) out[idx] = z + b2s;
    }
}

extern "C" void kernel_launch(void* const* d_in, const int* in_sizes, int n_in,
                              void* d_out, int out_size) {
    const float* rec  = (const float*)d_in[0];
    const float* sloc = (const float*)d_in[1];
    const float* emit = (const float*)d_in[2];
    const float* rloc = (const float*)d_in[3];
    const float* W1   = (const float*)d_in[4];
    const float* b1v  = (const float*)d_in[5];
    const float* W2   = (const float*)d_in[6];
    const float* b2v  = (const float*)d_in[7];
    float* out = (float*)d_out;

    int nb1 = in_sizes[0] / (NUM_R * LREC);       // B1
    if (nb1 < 1) nb1 = 1;
    if (nb1 > MAXB1) nb1 = MAXB1;
    int total = out_size;                         // B1*B2 samples
    int b2n = total / nb1;

    int b1shift = -1;
    if (b2n > 0 && (b2n & (b2n - 1)) == 0) {
        b1shift = 0;
        while ((1 << b1shift) != b2n) ++b1shift;
    }

    prep_kernel<<<NUM_R * nb1, 256>>>(W1, rec);

    int blocks = (total + SPB - 1) / SPB;

    // Launch tof with Programmatic Dependent Launch so its geometry phase
    // overlaps prep; fall back to a plain launch if PDL is unavailable.
    cudaLaunchConfig_t cfg = {};
    cfg.gridDim  = dim3((unsigned)blocks, 1, 1);
    cfg.blockDim = dim3(256, 1, 1);
    cfg.dynamicSmemBytes = 0;
    cfg.stream = 0;
    cudaLaunchAttribute at[1];
    at[0].id = cudaLaunchAttributeProgrammaticStreamSerialization;
    at[0].val.programmaticStreamSerializationAllowed = 1;
    cfg.attrs = at;
    cfg.numAttrs = 1;
    cudaError_t e = cudaLaunchKernelEx(&cfg, tof_kernel,
                                       sloc, emit, rloc, b1v, W2, b2v, out,
                                       total, b2n, b1shift);
    if (e != cudaSuccess) {
        (void)cudaGetLastError();   // clear sticky error
        tof_kernel<<<blocks, 256>>>(sloc, emit, rloc, b1v, W2, b2v, out,
                                    total, b2n, b1shift);
    }
}